// round 15
// baseline (speedup 1.0000x reference)
#include <cuda_runtime.h>
#include <cstdint>

#define NBATCH 2
#define WW 80
#define NTOK 6400
#define NHEADS 8
#define HD 16
#define ATTN_SCALE 0.25f
#define QK_SCALE (0.25f * 1.4426950408889634f)   // fold softmax scale * log2(e) into Q

// ---------------- scratch (static __device__ — no allocations) ----------------
__device__ float g_Q[(size_t)NBATCH * NHEADS * NTOK * HD];     // (b,h,tok,d)
__device__ float g_K[(size_t)NBATCH * NHEADS * NTOK * HD];
__device__ float g_V[(size_t)NBATCH * NHEADS * NTOK * HD];
__device__ float g_Osum[(size_t)NBATCH * NTOK * 128];          // (b,dest_tok, h*16+d)
__device__ float g_Wc[128 * 128];                              // wproj @ wfinal
__device__ float g_bc[128];                                    // 3*bproj@wfinal + bfinal
__device__ float g_Vc40[64 * 40 * 16];                         // per bh: column sums of V
__device__ float g_Vr40[64 * 40 * 16];                         // per bh: row sums of V
__device__ uint32_t g_Kp[(size_t)64 * 25 * 512];               // packed bf16x2 K tiles
__device__ uint32_t g_Vtp[(size_t)64 * 25 * 512];              // packed bf16x2 V^T tiles

__device__ __forceinline__ void load16(const float* __restrict__ p, float* r) {
#pragma unroll
    for (int i = 0; i < 4; i++) {
        float4 t = ((const float4*)p)[i];
        r[4 * i + 0] = t.x; r[4 * i + 1] = t.y; r[4 * i + 2] = t.z; r[4 * i + 3] = t.w;
    }
}

__device__ __forceinline__ uint32_t bf16x2(float lo, float hi) {
    uint32_t r;
    asm("cvt.rn.bf16x2.f32 %0, %1, %2;" : "=r"(r) : "f"(hi), "f"(lo));
    return r;
}
__device__ __forceinline__ float ex2f(float x) {
    float r; asm("ex2.approx.f32 %0, %1;" : "=f"(r) : "f"(x)); return r;
}
__device__ __forceinline__ void mma_bf16(
    float& c0, float& c1, float& c2, float& c3,
    uint32_t a0, uint32_t a1, uint32_t a2, uint32_t a3,
    uint32_t b0, uint32_t b1) {
    asm("mma.sync.aligned.m16n8k16.row.col.f32.bf16.bf16.f32 "
        "{%0,%1,%2,%3}, {%4,%5,%6,%7}, {%8,%9}, {%0,%1,%2,%3};"
        : "+f"(c0), "+f"(c1), "+f"(c2), "+f"(c3)
        : "r"(a0), "r"(a1), "r"(a2), "r"(a3), "r"(b0), "r"(b1));
}
__device__ __forceinline__ void split_pair(float a0, float a1, uint32_t& hi, uint32_t& lo) {
    hi = bf16x2(a0, a1);
    float h0 = __uint_as_float(hi << 16);
    float h1 = __uint_as_float(hi & 0xffff0000u);
    lo = bf16x2(a0 - h0, a1 - h1);
}

// ---------------- QKV projection via bf16x3 mma: X(12800,128) @ [wq|wkv](128,384) ----------------
__global__ __launch_bounds__(256) void qkv_mma_kernel(
    const float* __restrict__ X, const float* __restrict__ wq,
    const float* __restrict__ wkv) {
    __shared__ uint32_t AsH[128][9], AsL[128][9];
    __shared__ uint32_t BsH[64][9], BsL[64][9];
    const int m0 = blockIdx.x * 128;
    const int n0 = blockIdx.y * 64;
    const float* bsrc; int ld;
    if (n0 < 128) { bsrc = wq + n0; ld = 128; }
    else          { bsrc = wkv + (n0 - 128); ld = 256; }
    const int tid = threadIdx.x;
    const int wid = tid >> 5, lane = tid & 31;
    const int lr = lane >> 2, lc = lane & 3;
    float c[8][4];
#pragma unroll
    for (int j = 0; j < 8; j++)
#pragma unroll
        for (int i = 0; i < 4; i++) c[j][i] = 0.f;

    for (int kc = 0; kc < 8; kc++) {
        __syncthreads();
        {
            int row = tid >> 1, hf = tid & 1;
            const float* src = &X[(size_t)(m0 + row) * 128 + kc * 16 + hf * 8];
            float4 f0 = *(const float4*)src;
            float4 f1 = *(const float4*)(src + 4);
            uint32_t h, l;
            split_pair(f0.x, f0.y, h, l); AsH[row][hf * 4 + 0] = h; AsL[row][hf * 4 + 0] = l;
            split_pair(f0.z, f0.w, h, l); AsH[row][hf * 4 + 1] = h; AsL[row][hf * 4 + 1] = l;
            split_pair(f1.x, f1.y, h, l); AsH[row][hf * 4 + 2] = h; AsL[row][hf * 4 + 2] = l;
            split_pair(f1.z, f1.w, h, l); AsH[row][hf * 4 + 3] = h; AsL[row][hf * 4 + 3] = l;
        }
#pragma unroll
        for (int ee = 0; ee < 2; ee++) {
            int e = tid + ee * 256;
            int n = e & 63, kp = e >> 6;
            float b0 = bsrc[(size_t)(kc * 16 + 2 * kp) * ld + n];
            float b1 = bsrc[(size_t)(kc * 16 + 2 * kp + 1) * ld + n];
            uint32_t h, l; split_pair(b0, b1, h, l);
            BsH[n][kp] = h; BsL[n][kp] = l;
        }
        __syncthreads();
        const int rbase = wid * 16;
        uint32_t aH0 = AsH[rbase + lr][lc],     aH1 = AsH[rbase + lr + 8][lc];
        uint32_t aH2 = AsH[rbase + lr][lc + 4], aH3 = AsH[rbase + lr + 8][lc + 4];
        uint32_t aL0 = AsL[rbase + lr][lc],     aL1 = AsL[rbase + lr + 8][lc];
        uint32_t aL2 = AsL[rbase + lr][lc + 4], aL3 = AsL[rbase + lr + 8][lc + 4];
#pragma unroll
        for (int j = 0; j < 8; j++) {
            uint32_t bH0 = BsH[8 * j + lr][lc], bH1 = BsH[8 * j + lr][lc + 4];
            uint32_t bL0 = BsL[8 * j + lr][lc], bL1 = BsL[8 * j + lr][lc + 4];
            mma_bf16(c[j][0], c[j][1], c[j][2], c[j][3], aH0, aH1, aH2, aH3, bH0, bH1);
            mma_bf16(c[j][0], c[j][1], c[j][2], c[j][3], aL0, aL1, aL2, aL3, bH0, bH1);
            mma_bf16(c[j][0], c[j][1], c[j][2], c[j][3], aH0, aH1, aH2, aH3, bL0, bL1);
        }
    }
    const int region = n0 >> 7;
    float* dst = (region == 0) ? g_Q : (region == 1 ? g_K : g_V);
#pragma unroll
    for (int j = 0; j < 8; j++) {
        int jb = (n0 & 127) + 8 * j + 2 * lc;
        int h = jb >> 4, dd = jb & 15;
        int t0 = m0 + wid * 16 + lr;
        int b0i = t0 / NTOK, tok0 = t0 - b0i * NTOK;
        *(float2*)&dst[((size_t)(b0i * NHEADS + h) * NTOK + tok0) * HD + dd] =
            make_float2(c[j][0], c[j][1]);
        int t1 = t0 + 8;
        int b1i = t1 / NTOK, tok1 = t1 - b1i * NTOK;
        *(float2*)&dst[((size_t)(b1i * NHEADS + h) * NTOK + tok1) * HD + dd] =
            make_float2(c[j][2], c[j][3]);
    }
}

// ---------------- Wc = wproj @ wfinal ; bc ----------------
__global__ void wc_kernel(const float* __restrict__ wproj, const float* __restrict__ wfinal,
                          const float* __restrict__ bproj, const float* __restrict__ bfinal) {
    int i = blockIdx.x, j = threadIdx.x;
    float s = 0.f;
    for (int k = 0; k < 128; k++) s = fmaf(wproj[i * 128 + k], wfinal[k * 128 + j], s);
    g_Wc[i * 128 + j] = s;
    if (i == 0) {
        float sb = 0.f;
        for (int k = 0; k < 128; k++) sb = fmaf(bproj[k], wfinal[k * 128 + j], sb);
        g_bc[j] = 3.f * sb + bfinal[j];
    }
}

// ---------------- V row/col sums for p=40 rel-pos decomposition ----------------
__global__ void vsum40_kernel() {
    const int bh = blockIdx.x;
    const int b = bh >> 5, blk = (bh >> 3) & 3, h = bh & 7;
    const int bi = blk >> 1, bj = blk & 1;
    const int tid = threadIdx.x;                // 640
    const int idx = tid >> 4, dd = tid & 15;
    const float* Vb = g_V + (size_t)(b * NHEADS + h) * NTOK * HD;
    float sc = 0.f, sr = 0.f;
    for (int k2 = 0; k2 < 40; k2++) {
        sc += Vb[((bi * 40 + k2) * WW + bj * 40 + idx) * HD + dd];
        sr += Vb[((bi * 40 + idx) * WW + bj * 40 + k2) * HD + dd];
    }
    g_Vc40[bh * 640 + idx * 16 + dd] = sc;
    g_Vr40[bh * 640 + idx * 16 + dd] = sr;
}

// ---------------- pack K / V^T tiles to bf16x2 ----------------
// grid 1600 (= bh*25 + t), 256 threads.
__global__ __launch_bounds__(256) void pack40_kernel() {
    const int idx = blockIdx.x;
    const int bh = idx / 25, t = idx - bh * 25;
    const int b = bh >> 5, blk = (bh >> 3) & 3, h = bh & 7;
    const int bi = blk >> 1, bj = blk & 1;
    const size_t base = (size_t)(b * NHEADS + h) * NTOK;
    const int tid = threadIdx.x;
    uint32_t* Kdst = &g_Kp[(size_t)idx * 512];
    uint32_t* Vdst = &g_Vtp[(size_t)idx * 512];
    for (int e = tid; e < 512; e += 256) {
        int key = e >> 3, dp = e & 7;
        int kidx = t * 64 + key;
        int kr = kidx / 40, kc2 = kidx - kr * 40;
        float2 f = *(const float2*)&g_K[(base + (bi * 40 + kr) * WW + bj * 40 + kc2) * HD + 2 * dp];
        Kdst[e] = bf16x2(f.x, f.y);
    }
    for (int e = tid; e < 512; e += 256) {
        int d = e >> 5, k2 = e & 31;
        int kidx = t * 64 + 2 * k2;            // even -> pair never crosses a row of 40
        int kr = kidx / 40, kc2 = kidx - kr * 40;
        size_t tok = base + (bi * 40 + kr) * WW + bj * 40 + kc2;
        float lo = g_V[tok * HD + d];
        float hi = g_V[(tok + 1) * HD + d];
        Vdst[e] = bf16x2(lo, hi);
    }
}

// ---------------- attention for p in {4,8}: now ACCUMULATE onto attn40's output ----------------
template <int P, int HPC, bool ACCUM>
__global__ __launch_bounds__(P * P * HPC) void attn_small_kernel(
    const float* __restrict__ relw, const float* __restrict__ relh) {
    constexpr int N = P * P;
    constexpr int THREADS = N * HPC;
    constexpr int NBW = WW / P;
    constexpr int NB = NBW * NBW;
    constexpr int HG = NHEADS / HPC;
    __shared__ float Ks[HPC][N][16];
    __shared__ float Vs[HPC][N][16];
    __shared__ float Vc[HPC][P][16];
    __shared__ float Vr[HPC][P][16];
    __shared__ float rwT[16][2 * P];
    __shared__ float rhT[16][2 * P];

    const int cta = blockIdx.x;
    const int hg = cta % HG;
    const int blk = (cta / HG) % NB;
    const int b = cta / (HG * NB);
    const int bi = blk / NBW, bj = blk % NBW;
    const int tid = threadIdx.x;
    const int hh = tid / N;
    const int qi = tid - hh * N;
    const int h = hg * HPC + hh;

    for (int e = tid; e < (2 * P - 1) * 16; e += THREADS) {
        int rr = e >> 4, d = e & 15;
        rwT[d][rr] = relw[e];
        rhT[d][rr] = relh[e];
    }
    for (int e = tid; e < HPC * N * 4; e += THREADS) {
        int hl = e / (N * 4);
        int rem = e - hl * (N * 4);
        int key = rem >> 2, part = (rem & 3) << 2;
        int kr = key / P, kc = key - kr * P;
        int ktok = (bi * P + kr) * WW + bj * P + kc;
        size_t basek = (size_t)(b * NHEADS + hg * HPC + hl) * NTOK;
        *(float4*)&Ks[hl][key][part] = *(const float4*)&g_K[(basek + ktok) * HD + part];
        *(float4*)&Vs[hl][key][part] = *(const float4*)&g_V[(basek + ktok) * HD + part];
    }
    __syncthreads();
    for (int e = tid; e < HPC * P * 16; e += THREADS) {
        int hl = e / (P * 16);
        int rem = e - hl * (P * 16);
        int idx = rem >> 4, dd = rem & 15;
        float sc = 0.f, sr = 0.f;
#pragma unroll
        for (int k2 = 0; k2 < P; k2++) {
            sc += Vs[hl][k2 * P + idx][dd];
            sr += Vs[hl][idx * P + k2][dd];
        }
        Vc[hl][idx][dd] = sc;
        Vr[hl][idx][dd] = sr;
    }
    __syncthreads();

    const int r = qi / P, c = qi - (qi / P) * P;
    const int qtok = (bi * P + r) * WW + bj * P + c;
    const size_t base = (size_t)(b * NHEADS + h) * NTOK;
    float q[16];
    load16(&g_Q[(base + qtok) * HD], q);
    float o[16];
#pragma unroll
    for (int d = 0; d < 16; d++) o[d] = 0.f;
    float ssum = 0.f;

    for (int kk = 0; kk < N; kk++) {
        float kv[16];
        load16(&Ks[hh][kk][0], kv);
        float s = 0.f;
#pragma unroll
        for (int d = 0; d < 16; d++) s = fmaf(q[d], kv[d], s);
        float ew = __expf(s * ATTN_SCALE);
        ssum += ew;
        float vv[16];
        load16(&Vs[hh][kk][0], vv);
#pragma unroll
        for (int d = 0; d < 16; d++) o[d] = fmaf(ew, vv[d], o[d]);
    }
    float inv = 1.f / ssum;
#pragma unroll
    for (int d = 0; d < 16; d++) o[d] *= inv;

    const int cw = P - 1 - c, rw = P - 1 - r;
#pragma unroll 2
    for (int kc = 0; kc < P; kc++) {
        float w = 0.f, wh = 0.f;
#pragma unroll
        for (int d = 0; d < 16; d++) {
            w = fmaf(q[d], rwT[d][kc + cw], w);
            wh = fmaf(q[d], rhT[d][kc + rw], wh);
        }
        float vcv[16], vrv[16];
        load16(&Vc[hh][kc][0], vcv);
        load16(&Vr[hh][kc][0], vrv);
#pragma unroll
        for (int d = 0; d < 16; d++) {
            o[d] = fmaf(w, vcv[d], o[d]);
            o[d] = fmaf(wh, vrv[d], o[d]);
        }
    }
    const int dtok = (bi * NBW + bj) * N + qi;
    float* dst = g_Osum + ((size_t)b * NTOK + dtok) * 128 + h * HD;
#pragma unroll
    for (int d4 = 0; d4 < 4; d4++) {
        float4 val = make_float4(o[4 * d4], o[4 * d4 + 1], o[4 * d4 + 2], o[4 * d4 + 3]);
        if (ACCUM) {
            float4 cur = *(float4*)&dst[4 * d4];
            val.x += cur.x; val.y += cur.y; val.z += cur.z; val.w += cur.w;
        }
        *(float4*)&dst[4 * d4] = val;
    }
}

// ---------------- attention for p=40: bf16 mma, prepacked tiles, phase-union smem ----------------
// INITIALIZES g_Osum (pure store). KsU stride 12 -> conflict-free K-fragment LDS.
union S40 {
    struct {
        uint32_t KsU[2][768];      // stride 12 per key (bank-conflict-free)
        uint32_t VtU[2][576];      // stride 36 per d-row
    } mainp;
    struct {
        float Os[160][17];
        float rw[79 * 16], rh[79 * 16];
        float Vc[40][16], Vr[40][16];
    } epi;
};

__global__ __launch_bounds__(320, 3) void attn40_kernel(
    const float* __restrict__ relw, const float* __restrict__ relh) {
    __shared__ __align__(16) S40 s;

    const int bh = blockIdx.x / 10;
    const int qc = blockIdx.x - bh * 10;
    const int b = bh >> 5, blk = (bh >> 3) & 3, h = bh & 7;
    const int bi = blk >> 1, bj = blk & 1;
    const int tid = threadIdx.x;
    const size_t base = (size_t)(b * NHEADS + h) * NTOK;

    const int wid = tid >> 5, lane = tid & 31;
    const int lr = lane >> 2, lc = lane & 3;
    uint32_t qa0, qa1, qa2, qa3;
    {
        int qia = qc * 160 + wid * 16 + lr;
        int qib = qia + 8;
        int ra = qia / 40, ca = qia - ra * 40;
        int rb = qib / 40, cb = qib - rb * 40;
        const float* qpa = &g_Q[(base + (bi * 40 + ra) * WW + bj * 40 + ca) * HD];
        const float* qpb = &g_Q[(base + (bi * 40 + rb) * WW + bj * 40 + cb) * HD];
        float2 f;
        f = *(const float2*)&qpa[2 * lc];     qa0 = bf16x2(f.x * QK_SCALE, f.y * QK_SCALE);
        f = *(const float2*)&qpb[2 * lc];     qa1 = bf16x2(f.x * QK_SCALE, f.y * QK_SCALE);
        f = *(const float2*)&qpa[2 * lc + 8]; qa2 = bf16x2(f.x * QK_SCALE, f.y * QK_SCALE);
        f = *(const float2*)&qpb[2 * lc + 8]; qa3 = bf16x2(f.x * QK_SCALE, f.y * QK_SCALE);
    }
    float oc0[4] = {0.f, 0.f, 0.f, 0.f};
    float oc1[4] = {0.f, 0.f, 0.f, 0.f};
    float rsum0 = 0.f, rsum1 = 0.f;

    const uint32_t* Kp = &g_Kp[(size_t)bh * 25 * 512];
    const uint32_t* Vp = &g_Vtp[(size_t)bh * 25 * 512];
    const int j4 = (tid & 127) << 2;
    const int kkey = j4 >> 3, kdpb = j4 & 7;   // K smem slot (stride 12)

    uint4 pk, pv;
    if (tid < 128) {
        pk = *(const uint4*)&Kp[j4];
        *(uint4*)&s.mainp.KsU[0][kkey * 12 + kdpb] = pk;
    } else if (tid < 256) {
        pv = *(const uint4*)&Vp[j4];
        int d = j4 >> 5, k2 = j4 & 31;
        *(uint4*)&s.mainp.VtU[0][d * 36 + k2] = pv;
    }

    for (int t = 0; t < 25; t++) {
        if (t < 24) {
            if (tid < 128)      pk = *(const uint4*)&Kp[(t + 1) * 512 + j4];
            else if (tid < 256) pv = *(const uint4*)&Vp[(t + 1) * 512 + j4];
        }
        __syncthreads();
        const int cb = t & 1;

        uint32_t p[8][2];
#pragma unroll
        for (int g = 0; g < 8; g++) {
            float c0 = 0.f, c1 = 0.f, c2 = 0.f, c3 = 0.f;
            uint32_t kb0 = s.mainp.KsU[cb][(8 * g + lr) * 12 + lc];
            uint32_t kb1 = s.mainp.KsU[cb][(8 * g + lr) * 12 + lc + 4];
            mma_bf16(c0, c1, c2, c3, qa0, qa1, qa2, qa3, kb0, kb1);
            float e0 = ex2f(c0), e1 = ex2f(c1), e2 = ex2f(c2), e3 = ex2f(c3);
            rsum0 += e0 + e1;
            rsum1 += e2 + e3;
            p[g][0] = bf16x2(e0, e1);
            p[g][1] = bf16x2(e2, e3);
        }
#pragma unroll
        for (int gp = 0; gp < 4; gp++) {
            uint32_t a0 = p[2 * gp][0], a1 = p[2 * gp][1];
            uint32_t a2 = p[2 * gp + 1][0], a3 = p[2 * gp + 1][1];
            uint32_t vb0 = s.mainp.VtU[cb][lr * 36 + 8 * gp + lc];
            uint32_t vb1 = s.mainp.VtU[cb][lr * 36 + 8 * gp + lc + 4];
            mma_bf16(oc0[0], oc0[1], oc0[2], oc0[3], a0, a1, a2, a3, vb0, vb1);
            vb0 = s.mainp.VtU[cb][(8 + lr) * 36 + 8 * gp + lc];
            vb1 = s.mainp.VtU[cb][(8 + lr) * 36 + 8 * gp + lc + 4];
            mma_bf16(oc1[0], oc1[1], oc1[2], oc1[3], a0, a1, a2, a3, vb0, vb1);
        }
        if (t < 24) {
            const int nb = (t + 1) & 1;
            if (tid < 128) {
                *(uint4*)&s.mainp.KsU[nb][kkey * 12 + kdpb] = pk;
            } else if (tid < 256) {
                int d = j4 >> 5, k2 = j4 & 31;
                *(uint4*)&s.mainp.VtU[nb][d * 36 + k2] = pv;
            }
        }
    }
    rsum0 += __shfl_xor_sync(0xffffffffu, rsum0, 1);
    rsum0 += __shfl_xor_sync(0xffffffffu, rsum0, 2);
    rsum1 += __shfl_xor_sync(0xffffffffu, rsum1, 1);
    rsum1 += __shfl_xor_sync(0xffffffffu, rsum1, 2);
    float inv0 = 1.f / rsum0, inv1 = 1.f / rsum1;

    // ---- phase switch: main-loop buffers dead; load epilogue tables ----
    __syncthreads();
    for (int e = tid; e < 79 * 16; e += 320) { s.epi.rw[e] = relw[e]; s.epi.rh[e] = relh[e]; }
    for (int e = tid; e < 640; e += 320) {
        ((float*)s.epi.Vc)[e] = g_Vc40[bh * 640 + e];
        ((float*)s.epi.Vr)[e] = g_Vr40[bh * 640 + e];
    }
    {
        int ql = wid * 16;
        s.epi.Os[ql + lr][2 * lc]         = oc0[0] * inv0;
        s.epi.Os[ql + lr][2 * lc + 1]     = oc0[1] * inv0;
        s.epi.Os[ql + lr + 8][2 * lc]     = oc0[2] * inv1;
        s.epi.Os[ql + lr + 8][2 * lc + 1] = oc0[3] * inv1;
        s.epi.Os[ql + lr][2 * lc + 8]     = oc1[0] * inv0;
        s.epi.Os[ql + lr][2 * lc + 9]     = oc1[1] * inv0;
        s.epi.Os[ql + lr + 8][2 * lc + 8] = oc1[2] * inv1;
        s.epi.Os[ql + lr + 8][2 * lc + 9] = oc1[3] * inv1;
    }
    __syncthreads();

    // fp32 rel-pos epilogue: 2 threads per query; PURE STORE (initializes g_Osum)
    const int qloc = tid >> 1, half = tid & 1;
    const int qi = qc * 160 + qloc;
    const int r = qi / 40, c = qi - r * 40;
    float q[16];
    load16(&g_Q[(base + (bi * 40 + r) * WW + bj * 40 + c) * HD], q);
    float o[8] = {0.f, 0.f, 0.f, 0.f, 0.f, 0.f, 0.f, 0.f};
    const int off = half ? (39 - r) : (39 - c);
    const float* tbl = half ? s.epi.rh : s.epi.rw;
#pragma unroll 2
    for (int kc = 0; kc < 40; kc++) {
        const float* tp = &tbl[(kc + off) * 16];
        float mine = 0.f;
#pragma unroll
        for (int d = 0; d < 16; d++) mine = fmaf(q[d], tp[d], mine);
        float other = __shfl_xor_sync(0xffffffffu, mine, 1);
        float w  = half ? other : mine;
        float wh = half ? mine  : other;
#pragma unroll
        for (int j = 0; j < 8; j++)
            o[j] = fmaf(w, s.epi.Vc[kc][half * 8 + j], fmaf(wh, s.epi.Vr[kc][half * 8 + j], o[j]));
    }
    const int pbase = (bi * 2 + bj) * 1600;
    float* dst = &g_Osum[((size_t)b * NTOK + pbase + qi) * 128 + h * HD + half * 8];
#pragma unroll
    for (int j4b = 0; j4b < 2; j4b++) {
        float4 val = make_float4(
            o[4 * j4b + 0] + s.epi.Os[qloc][half * 8 + 4 * j4b + 0],
            o[4 * j4b + 1] + s.epi.Os[qloc][half * 8 + 4 * j4b + 1],
            o[4 * j4b + 2] + s.epi.Os[qloc][half * 8 + 4 * j4b + 2],
            o[4 * j4b + 3] + s.epi.Os[qloc][half * 8 + 4 * j4b + 3]);
        *(float4*)&dst[4 * j4b] = val;
    }
}

// ---------------- final via bf16x3 mma: out = Osum @ Wc + bc ----------------
__global__ __launch_bounds__(256) void final_mma_kernel(float* __restrict__ out) {
    __shared__ uint32_t AsH[128][9], AsL[128][9];
    __shared__ uint32_t BsH[64][9], BsL[64][9];
    const int m0 = blockIdx.x * 128;
    const int n0 = blockIdx.y * 64;
    const int tid = threadIdx.x;
    const int wid = tid >> 5, lane = tid & 31;
    const int lr = lane >> 2, lc = lane & 3;
    float c[8][4];
#pragma unroll
    for (int j = 0; j < 8; j++)
#pragma unroll
        for (int i = 0; i < 4; i++) c[j][i] = 0.f;

    for (int kc = 0; kc < 8; kc++) {
        __syncthreads();
        {
            int row = tid >> 1, hf = tid & 1;
            const float* src = &g_Osum[(size_t)(m0 + row) * 128 + kc * 16 + hf * 8];
            float4 f0 = *(const float4*)src;
            float4 f1 = *(const float4*)(src + 4);
            uint32_t h, l;
            split_pair(f0.x, f0.y, h, l); AsH[row][hf * 4 + 0] = h; AsL[row][hf * 4 + 0] = l;
            split_pair(f0.z, f0.w, h, l); AsH[row][hf * 4 + 1] = h; AsL[row][hf * 4 + 1] = l;
            split_pair(f1.x, f1.y, h, l); AsH[row][hf * 4 + 2] = h; AsL[row][hf * 4 + 2] = l;
            split_pair(f1.z, f1.w, h, l); AsH[row][hf * 4 + 3] = h; AsL[row][hf * 4 + 3] = l;
        }
#pragma unroll
        for (int ee = 0; ee < 2; ee++) {
            int e = tid + ee * 256;
            int n = e & 63, kp = e >> 6;
            float b0 = g_Wc[(size_t)(kc * 16 + 2 * kp) * 128 + n0 + n];
            float b1 = g_Wc[(size_t)(kc * 16 + 2 * kp + 1) * 128 + n0 + n];
            uint32_t h, l; split_pair(b0, b1, h, l);
            BsH[n][kp] = h; BsL[n][kp] = l;
        }
        __syncthreads();
        const int rbase = wid * 16;
        uint32_t aH0 = AsH[rbase + lr][lc],     aH1 = AsH[rbase + lr + 8][lc];
        uint32_t aH2 = AsH[rbase + lr][lc + 4], aH3 = AsH[rbase + lr + 8][lc + 4];
        uint32_t aL0 = AsL[rbase + lr][lc],     aL1 = AsL[rbase + lr + 8][lc];
        uint32_t aL2 = AsL[rbase + lr][lc + 4], aL3 = AsL[rbase + lr + 8][lc + 4];
#pragma unroll
        for (int j = 0; j < 8; j++) {
            uint32_t bH0 = BsH[8 * j + lr][lc], bH1 = BsH[8 * j + lr][lc + 4];
            uint32_t bL0 = BsL[8 * j + lr][lc], bL1 = BsL[8 * j + lr][lc + 4];
            mma_bf16(c[j][0], c[j][1], c[j][2], c[j][3], aH0, aH1, aH2, aH3, bH0, bH1);
            mma_bf16(c[j][0], c[j][1], c[j][2], c[j][3], aL0, aL1, aL2, aL3, bH0, bH1);
            mma_bf16(c[j][0], c[j][1], c[j][2], c[j][3], aH0, aH1, aH2, aH3, bL0, bL1);
        }
    }
#pragma unroll
    for (int j = 0; j < 8; j++) {
        int ncol = n0 + 8 * j + 2 * lc;
        float b0v = g_bc[ncol], b1v = g_bc[ncol + 1];
        int t0 = m0 + wid * 16 + lr;
        *(float2*)&out[(size_t)t0 * 128 + ncol] = make_float2(c[j][0] + b0v, c[j][1] + b1v);
        *(float2*)&out[(size_t)(t0 + 8) * 128 + ncol] = make_float2(c[j][2] + b0v, c[j][3] + b1v);
    }
}

// ---------------- launcher (attn40 at launch index 3 -> gets profiled) ----------------
extern "C" void kernel_launch(void* const* d_in, const int* in_sizes, int n_in,
                              void* d_out, int out_size) {
    (void)in_sizes; (void)n_in; (void)out_size;
    const float* x      = (const float*)d_in[0];
    const float* wq     = (const float*)d_in[1];
    const float* wkv    = (const float*)d_in[2];
    const float* wproj  = (const float*)d_in[3];
    const float* bproj  = (const float*)d_in[4];
    const float* wfinal = (const float*)d_in[5];
    const float* bfinal = (const float*)d_in[6];
    const float* rw0 = (const float*)d_in[7];
    const float* rh0 = (const float*)d_in[8];
    const float* rw1 = (const float*)d_in[9];
    const float* rh1 = (const float*)d_in[10];
    const float* rw2 = (const float*)d_in[11];
    const float* rh2 = (const float*)d_in[12];
    float* out = (float*)d_out;

    qkv_mma_kernel<<<dim3(100, 6), 256>>>(x, wq, wkv);            // 0
    pack40_kernel<<<1600, 256>>>();                                // 1
    vsum40_kernel<<<64, 640>>>();                                  // 2
    attn40_kernel<<<640, 320>>>(rw2, rh2);                         // 3  (STORES g_Osum)
    attn_small_kernel<4, 8, true><<<800, 128>>>(rw0, rh0);         // 4  (accumulate)
    attn_small_kernel<8, 2, true><<<800, 128>>>(rw1, rh1);         // 5  (accumulate)
    wc_kernel<<<128, 128>>>(wproj, wfinal, bproj, bfinal);         // 6
    final_mma_kernel<<<dim3(100, 2), 256>>>(out);                  // 7
}

// round 17
// speedup vs baseline: 1.0443x; 1.0443x over previous
#include <cuda_runtime.h>
#include <cstdint>

#define NBATCH 2
#define WW 80
#define NTOK 6400
#define NHEADS 8
#define HD 16
#define ATTN_SCALE 0.25f
#define QK_SCALE (0.25f * 1.4426950408889634f)   // fold softmax scale * log2(e) into Q

// ---------------- scratch (static __device__ — no allocations) ----------------
__device__ float g_Q[(size_t)NBATCH * NHEADS * NTOK * HD];     // (b,h,tok,d)
__device__ float g_K[(size_t)NBATCH * NHEADS * NTOK * HD];
__device__ float g_V[(size_t)NBATCH * NHEADS * NTOK * HD];
__device__ float g_Osum[(size_t)NBATCH * NTOK * 128];          // (b,dest_tok, h*16+d)
__device__ float g_Wc[128 * 128];                              // wproj @ wfinal
__device__ float g_bc[128];                                    // 3*bproj@wfinal + bfinal
__device__ float g_Vc40[64 * 40 * 16];                         // per bh: column sums of V
__device__ float g_Vr40[64 * 40 * 16];                         // per bh: row sums of V
__device__ uint32_t g_Kp[(size_t)64 * 25 * 512];               // packed bf16x2 K tiles
__device__ uint32_t g_Vtp[(size_t)64 * 25 * 512];              // packed bf16x2 V^T tiles

__device__ __forceinline__ void load16(const float* __restrict__ p, float* r) {
#pragma unroll
    for (int i = 0; i < 4; i++) {
        float4 t = ((const float4*)p)[i];
        r[4 * i + 0] = t.x; r[4 * i + 1] = t.y; r[4 * i + 2] = t.z; r[4 * i + 3] = t.w;
    }
}

__device__ __forceinline__ uint32_t bf16x2(float lo, float hi) {
    uint32_t r;
    asm("cvt.rn.bf16x2.f32 %0, %1, %2;" : "=r"(r) : "f"(hi), "f"(lo));
    return r;
}
__device__ __forceinline__ float ex2f(float x) {
    float r; asm("ex2.approx.f32 %0, %1;" : "=f"(r) : "f"(x)); return r;
}
__device__ __forceinline__ void mma_bf16(
    float& c0, float& c1, float& c2, float& c3,
    uint32_t a0, uint32_t a1, uint32_t a2, uint32_t a3,
    uint32_t b0, uint32_t b1) {
    asm("mma.sync.aligned.m16n8k16.row.col.f32.bf16.bf16.f32 "
        "{%0,%1,%2,%3}, {%4,%5,%6,%7}, {%8,%9}, {%0,%1,%2,%3};"
        : "+f"(c0), "+f"(c1), "+f"(c2), "+f"(c3)
        : "r"(a0), "r"(a1), "r"(a2), "r"(a3), "r"(b0), "r"(b1));
}
__device__ __forceinline__ void split_pair(float a0, float a1, uint32_t& hi, uint32_t& lo) {
    hi = bf16x2(a0, a1);
    float h0 = __uint_as_float(hi << 16);
    float h1 = __uint_as_float(hi & 0xffff0000u);
    lo = bf16x2(a0 - h0, a1 - h1);
}

// ---------------- QKV projection via bf16x3 mma: X(12800,128) @ [wq|wkv](128,384) ----------------
__global__ __launch_bounds__(256) void qkv_mma_kernel(
    const float* __restrict__ X, const float* __restrict__ wq,
    const float* __restrict__ wkv) {
    __shared__ uint32_t AsH[128][9], AsL[128][9];
    __shared__ uint32_t BsH[64][9], BsL[64][9];
    const int m0 = blockIdx.x * 128;
    const int n0 = blockIdx.y * 64;
    const float* bsrc; int ld;
    if (n0 < 128) { bsrc = wq + n0; ld = 128; }
    else          { bsrc = wkv + (n0 - 128); ld = 256; }
    const int tid = threadIdx.x;
    const int wid = tid >> 5, lane = tid & 31;
    const int lr = lane >> 2, lc = lane & 3;
    float c[8][4];
#pragma unroll
    for (int j = 0; j < 8; j++)
#pragma unroll
        for (int i = 0; i < 4; i++) c[j][i] = 0.f;

    for (int kc = 0; kc < 8; kc++) {
        __syncthreads();
        {
            int row = tid >> 1, hf = tid & 1;
            const float* src = &X[(size_t)(m0 + row) * 128 + kc * 16 + hf * 8];
            float4 f0 = *(const float4*)src;
            float4 f1 = *(const float4*)(src + 4);
            uint32_t h, l;
            split_pair(f0.x, f0.y, h, l); AsH[row][hf * 4 + 0] = h; AsL[row][hf * 4 + 0] = l;
            split_pair(f0.z, f0.w, h, l); AsH[row][hf * 4 + 1] = h; AsL[row][hf * 4 + 1] = l;
            split_pair(f1.x, f1.y, h, l); AsH[row][hf * 4 + 2] = h; AsL[row][hf * 4 + 2] = l;
            split_pair(f1.z, f1.w, h, l); AsH[row][hf * 4 + 3] = h; AsL[row][hf * 4 + 3] = l;
        }
#pragma unroll
        for (int ee = 0; ee < 2; ee++) {
            int e = tid + ee * 256;
            int n = e & 63, kp = e >> 6;
            float b0 = bsrc[(size_t)(kc * 16 + 2 * kp) * ld + n];
            float b1 = bsrc[(size_t)(kc * 16 + 2 * kp + 1) * ld + n];
            uint32_t h, l; split_pair(b0, b1, h, l);
            BsH[n][kp] = h; BsL[n][kp] = l;
        }
        __syncthreads();
        const int rbase = wid * 16;
        uint32_t aH0 = AsH[rbase + lr][lc],     aH1 = AsH[rbase + lr + 8][lc];
        uint32_t aH2 = AsH[rbase + lr][lc + 4], aH3 = AsH[rbase + lr + 8][lc + 4];
        uint32_t aL0 = AsL[rbase + lr][lc],     aL1 = AsL[rbase + lr + 8][lc];
        uint32_t aL2 = AsL[rbase + lr][lc + 4], aL3 = AsL[rbase + lr + 8][lc + 4];
#pragma unroll
        for (int j = 0; j < 8; j++) {
            uint32_t bH0 = BsH[8 * j + lr][lc], bH1 = BsH[8 * j + lr][lc + 4];
            uint32_t bL0 = BsL[8 * j + lr][lc], bL1 = BsL[8 * j + lr][lc + 4];
            mma_bf16(c[j][0], c[j][1], c[j][2], c[j][3], aH0, aH1, aH2, aH3, bH0, bH1);
            mma_bf16(c[j][0], c[j][1], c[j][2], c[j][3], aL0, aL1, aL2, aL3, bH0, bH1);
            mma_bf16(c[j][0], c[j][1], c[j][2], c[j][3], aH0, aH1, aH2, aH3, bL0, bL1);
        }
    }
    const int region = n0 >> 7;
    float* dst = (region == 0) ? g_Q : (region == 1 ? g_K : g_V);
#pragma unroll
    for (int j = 0; j < 8; j++) {
        int jb = (n0 & 127) + 8 * j + 2 * lc;
        int h = jb >> 4, dd = jb & 15;
        int t0 = m0 + wid * 16 + lr;
        int b0i = t0 / NTOK, tok0 = t0 - b0i * NTOK;
        *(float2*)&dst[((size_t)(b0i * NHEADS + h) * NTOK + tok0) * HD + dd] =
            make_float2(c[j][0], c[j][1]);
        int t1 = t0 + 8;
        int b1i = t1 / NTOK, tok1 = t1 - b1i * NTOK;
        *(float2*)&dst[((size_t)(b1i * NHEADS + h) * NTOK + tok1) * HD + dd] =
            make_float2(c[j][2], c[j][3]);
    }
}

// ---------------- Wc = wproj @ wfinal ; bc ----------------
__global__ void wc_kernel(const float* __restrict__ wproj, const float* __restrict__ wfinal,
                          const float* __restrict__ bproj, const float* __restrict__ bfinal) {
    int i = blockIdx.x, j = threadIdx.x;
    float s = 0.f;
    for (int k = 0; k < 128; k++) s = fmaf(wproj[i * 128 + k], wfinal[k * 128 + j], s);
    g_Wc[i * 128 + j] = s;
    if (i == 0) {
        float sb = 0.f;
        for (int k = 0; k < 128; k++) sb = fmaf(bproj[k], wfinal[k * 128 + j], sb);
        g_bc[j] = 3.f * sb + bfinal[j];
    }
}

// ---------------- V row/col sums for p=40 rel-pos decomposition ----------------
__global__ void vsum40_kernel() {
    const int bh = blockIdx.x;
    const int b = bh >> 5, blk = (bh >> 3) & 3, h = bh & 7;
    const int bi = blk >> 1, bj = blk & 1;
    const int tid = threadIdx.x;                // 640
    const int idx = tid >> 4, dd = tid & 15;
    const float* Vb = g_V + (size_t)(b * NHEADS + h) * NTOK * HD;
    float sc = 0.f, sr = 0.f;
    for (int k2 = 0; k2 < 40; k2++) {
        sc += Vb[((bi * 40 + k2) * WW + bj * 40 + idx) * HD + dd];
        sr += Vb[((bi * 40 + idx) * WW + bj * 40 + k2) * HD + dd];
    }
    g_Vc40[bh * 640 + idx * 16 + dd] = sc;
    g_Vr40[bh * 640 + idx * 16 + dd] = sr;
}

// ---------------- pack K / V^T tiles to bf16x2 ----------------
// grid 1600 (= bh*25 + t), 256 threads.
__global__ __launch_bounds__(256) void pack40_kernel() {
    const int idx = blockIdx.x;
    const int bh = idx / 25, t = idx - bh * 25;
    const int b = bh >> 5, blk = (bh >> 3) & 3, h = bh & 7;
    const int bi = blk >> 1, bj = blk & 1;
    const size_t base = (size_t)(b * NHEADS + h) * NTOK;
    const int tid = threadIdx.x;
    uint32_t* Kdst = &g_Kp[(size_t)idx * 512];
    uint32_t* Vdst = &g_Vtp[(size_t)idx * 512];
    for (int e = tid; e < 512; e += 256) {
        int key = e >> 3, dp = e & 7;
        int kidx = t * 64 + key;
        int kr = kidx / 40, kc2 = kidx - kr * 40;
        float2 f = *(const float2*)&g_K[(base + (bi * 40 + kr) * WW + bj * 40 + kc2) * HD + 2 * dp];
        Kdst[e] = bf16x2(f.x, f.y);
    }
    for (int e = tid; e < 512; e += 256) {
        int d = e >> 5, k2 = e & 31;
        int kidx = t * 64 + 2 * k2;            // even -> pair never crosses a row of 40
        int kr = kidx / 40, kc2 = kidx - kr * 40;
        size_t tok = base + (bi * 40 + kr) * WW + bj * 40 + kc2;
        float lo = g_V[tok * HD + d];
        float hi = g_V[(tok + 1) * HD + d];
        Vdst[e] = bf16x2(lo, hi);
    }
}

// ---------------- attention for p in {4,8}: ACCUMULATE onto attn40's output ----------------
template <int P, int HPC, bool ACCUM>
__global__ __launch_bounds__(P * P * HPC) void attn_small_kernel(
    const float* __restrict__ relw, const float* __restrict__ relh) {
    constexpr int N = P * P;
    constexpr int THREADS = N * HPC;
    constexpr int NBW = WW / P;
    constexpr int NB = NBW * NBW;
    constexpr int HG = NHEADS / HPC;
    __shared__ float Ks[HPC][N][16];
    __shared__ float Vs[HPC][N][16];
    __shared__ float Vc[HPC][P][16];
    __shared__ float Vr[HPC][P][16];
    __shared__ float rwT[16][2 * P];
    __shared__ float rhT[16][2 * P];

    const int cta = blockIdx.x;
    const int hg = cta % HG;
    const int blk = (cta / HG) % NB;
    const int b = cta / (HG * NB);
    const int bi = blk / NBW, bj = blk % NBW;
    const int tid = threadIdx.x;
    const int hh = tid / N;
    const int qi = tid - hh * N;
    const int h = hg * HPC + hh;

    for (int e = tid; e < (2 * P - 1) * 16; e += THREADS) {
        int rr = e >> 4, d = e & 15;
        rwT[d][rr] = relw[e];
        rhT[d][rr] = relh[e];
    }
    for (int e = tid; e < HPC * N * 4; e += THREADS) {
        int hl = e / (N * 4);
        int rem = e - hl * (N * 4);
        int key = rem >> 2, part = (rem & 3) << 2;
        int kr = key / P, kc = key - kr * P;
        int ktok = (bi * P + kr) * WW + bj * P + kc;
        size_t basek = (size_t)(b * NHEADS + hg * HPC + hl) * NTOK;
        *(float4*)&Ks[hl][key][part] = *(const float4*)&g_K[(basek + ktok) * HD + part];
        *(float4*)&Vs[hl][key][part] = *(const float4*)&g_V[(basek + ktok) * HD + part];
    }
    __syncthreads();
    for (int e = tid; e < HPC * P * 16; e += THREADS) {
        int hl = e / (P * 16);
        int rem = e - hl * (P * 16);
        int idx = rem >> 4, dd = rem & 15;
        float sc = 0.f, sr = 0.f;
#pragma unroll
        for (int k2 = 0; k2 < P; k2++) {
            sc += Vs[hl][k2 * P + idx][dd];
            sr += Vs[hl][idx * P + k2][dd];
        }
        Vc[hl][idx][dd] = sc;
        Vr[hl][idx][dd] = sr;
    }
    __syncthreads();

    const int r = qi / P, c = qi - (qi / P) * P;
    const int qtok = (bi * P + r) * WW + bj * P + c;
    const size_t base = (size_t)(b * NHEADS + h) * NTOK;
    float q[16];
    load16(&g_Q[(base + qtok) * HD], q);
    float o[16];
#pragma unroll
    for (int d = 0; d < 16; d++) o[d] = 0.f;
    float ssum = 0.f;

    for (int kk = 0; kk < N; kk++) {
        float kv[16];
        load16(&Ks[hh][kk][0], kv);
        float s = 0.f;
#pragma unroll
        for (int d = 0; d < 16; d++) s = fmaf(q[d], kv[d], s);
        float ew = __expf(s * ATTN_SCALE);
        ssum += ew;
        float vv[16];
        load16(&Vs[hh][kk][0], vv);
#pragma unroll
        for (int d = 0; d < 16; d++) o[d] = fmaf(ew, vv[d], o[d]);
    }
    float inv = 1.f / ssum;
#pragma unroll
    for (int d = 0; d < 16; d++) o[d] *= inv;

    const int cw = P - 1 - c, rw = P - 1 - r;
#pragma unroll 2
    for (int kc = 0; kc < P; kc++) {
        float w = 0.f, wh = 0.f;
#pragma unroll
        for (int d = 0; d < 16; d++) {
            w = fmaf(q[d], rwT[d][kc + cw], w);
            wh = fmaf(q[d], rhT[d][kc + rw], wh);
        }
        float vcv[16], vrv[16];
        load16(&Vc[hh][kc][0], vcv);
        load16(&Vr[hh][kc][0], vrv);
#pragma unroll
        for (int d = 0; d < 16; d++) {
            o[d] = fmaf(w, vcv[d], o[d]);
            o[d] = fmaf(wh, vrv[d], o[d]);
        }
    }
    const int dtok = (bi * NBW + bj) * N + qi;
    float* dst = g_Osum + ((size_t)b * NTOK + dtok) * 128 + h * HD;
#pragma unroll
    for (int d4 = 0; d4 < 4; d4++) {
        float4 val = make_float4(o[4 * d4], o[4 * d4 + 1], o[4 * d4 + 2], o[4 * d4 + 3]);
        if (ACCUM) {
            float4 cur = *(float4*)&dst[4 * d4];
            val.x += cur.x; val.y += cur.y; val.z += cur.z; val.w += cur.w;
        }
        *(float4*)&dst[4 * d4] = val;
    }
}

// ---------------- attention for p=40: bf16 mma, interleaved QK/PV, mma rowsums ----------------
// regs trimmed (p[8][2] -> p[4]; rsum via ones-mma) to reach 4 CTAs/SM.
// Softmax output stored directly to g_Osum; epilogue RMWs it (CTA-coherent after sync).
#define ONES_BF16X2 0x3F803F80u
union S40 {
    struct {
        uint32_t KsU[2][768];      // stride 12 per key (bank-conflict-free)
        uint32_t VtU[2][576];      // stride 36 per d-row
    } mainp;
    struct {
        float rw[79 * 16], rh[79 * 16];
        float Vc[40][16], Vr[40][16];
    } epi;
};

__global__ __launch_bounds__(320, 4) void attn40_kernel(
    const float* __restrict__ relw, const float* __restrict__ relh) {
    __shared__ __align__(16) S40 s;

    const int bh = blockIdx.x / 10;
    const int qc = blockIdx.x - bh * 10;
    const int b = bh >> 5, blk = (bh >> 3) & 3, h = bh & 7;
    const int bi = blk >> 1, bj = blk & 1;
    const int tid = threadIdx.x;
    const size_t base = (size_t)(b * NHEADS + h) * NTOK;

    const int wid = tid >> 5, lane = tid & 31;
    const int lr = lane >> 2, lc = lane & 3;
    uint32_t qa0, qa1, qa2, qa3;
    {
        int qia = qc * 160 + wid * 16 + lr;
        int qib = qia + 8;
        int ra = qia / 40, ca = qia - ra * 40;
        int rb = qib / 40, cb = qib - rb * 40;
        const float* qpa = &g_Q[(base + (bi * 40 + ra) * WW + bj * 40 + ca) * HD];
        const float* qpb = &g_Q[(base + (bi * 40 + rb) * WW + bj * 40 + cb) * HD];
        float2 f;
        f = *(const float2*)&qpa[2 * lc];     qa0 = bf16x2(f.x * QK_SCALE, f.y * QK_SCALE);
        f = *(const float2*)&qpb[2 * lc];     qa1 = bf16x2(f.x * QK_SCALE, f.y * QK_SCALE);
        f = *(const float2*)&qpa[2 * lc + 8]; qa2 = bf16x2(f.x * QK_SCALE, f.y * QK_SCALE);
        f = *(const float2*)&qpb[2 * lc + 8]; qa3 = bf16x2(f.x * QK_SCALE, f.y * QK_SCALE);
    }
    float oc0[4] = {0.f, 0.f, 0.f, 0.f};
    float oc1[4] = {0.f, 0.f, 0.f, 0.f};
    float rs[4] = {0.f, 0.f, 0.f, 0.f};        // rowsum accumulator (ones-mma)

    const uint32_t* Kp = &g_Kp[(size_t)bh * 25 * 512];
    const uint32_t* Vp = &g_Vtp[(size_t)bh * 25 * 512];
    const int j4 = (tid & 127) << 2;
    const int kslot = (j4 >> 3) * 12 + (j4 & 7);   // K smem slot (stride 12)
    const int vslot = (j4 >> 5) * 36 + (j4 & 31);  // V smem slot (stride 36)

    uint4 pk, pv;
    if (tid < 128) {
        pk = *(const uint4*)&Kp[j4];
        *(uint4*)&s.mainp.KsU[0][kslot] = pk;
    } else if (tid < 256) {
        pv = *(const uint4*)&Vp[j4];
        *(uint4*)&s.mainp.VtU[0][vslot] = pv;
    }

    for (int t = 0; t < 25; t++) {
        if (t < 24) {
            if (tid < 128)      pk = *(const uint4*)&Kp[(t + 1) * 512 + j4];
            else if (tid < 256) pv = *(const uint4*)&Vp[(t + 1) * 512 + j4];
        }
        __syncthreads();
        const int cb = t & 1;

#pragma unroll
        for (int gp = 0; gp < 4; gp++) {
            uint32_t p0, p1, p2, p3;
            {
                float c0 = 0.f, c1 = 0.f, c2 = 0.f, c3 = 0.f;
                uint32_t kb0 = s.mainp.KsU[cb][(16 * gp + lr) * 12 + lc];
                uint32_t kb1 = s.mainp.KsU[cb][(16 * gp + lr) * 12 + lc + 4];
                mma_bf16(c0, c1, c2, c3, qa0, qa1, qa2, qa3, kb0, kb1);
                p0 = bf16x2(ex2f(c0), ex2f(c1));
                p1 = bf16x2(ex2f(c2), ex2f(c3));
            }
            {
                float c0 = 0.f, c1 = 0.f, c2 = 0.f, c3 = 0.f;
                uint32_t kb0 = s.mainp.KsU[cb][(16 * gp + 8 + lr) * 12 + lc];
                uint32_t kb1 = s.mainp.KsU[cb][(16 * gp + 8 + lr) * 12 + lc + 4];
                mma_bf16(c0, c1, c2, c3, qa0, qa1, qa2, qa3, kb0, kb1);
                p2 = bf16x2(ex2f(c0), ex2f(c1));
                p3 = bf16x2(ex2f(c2), ex2f(c3));
            }
            // rowsum: B = ones -> every output col = rowsum; accumulates across loop
            mma_bf16(rs[0], rs[1], rs[2], rs[3], p0, p1, p2, p3, ONES_BF16X2, ONES_BF16X2);
            // PV
            uint32_t vb0 = s.mainp.VtU[cb][lr * 36 + 8 * gp + lc];
            uint32_t vb1 = s.mainp.VtU[cb][lr * 36 + 8 * gp + lc + 4];
            mma_bf16(oc0[0], oc0[1], oc0[2], oc0[3], p0, p1, p2, p3, vb0, vb1);
            vb0 = s.mainp.VtU[cb][(8 + lr) * 36 + 8 * gp + lc];
            vb1 = s.mainp.VtU[cb][(8 + lr) * 36 + 8 * gp + lc + 4];
            mma_bf16(oc1[0], oc1[1], oc1[2], oc1[3], p0, p1, p2, p3, vb0, vb1);
        }
        if (t < 24) {
            const int nb = (t + 1) & 1;
            if (tid < 128) {
                *(uint4*)&s.mainp.KsU[nb][kslot] = pk;
            } else if (tid < 256) {
                *(uint4*)&s.mainp.VtU[nb][vslot] = pv;
            }
        }
    }
    const float inv0 = 1.f / rs[0];             // rowsum(q row lr) — same in every lane of quad
    const float inv1 = 1.f / rs[2];             // rowsum(q row lr+8)
    const int pbase = (bi * 2 + bj) * 1600;

    // ---- store softmax part directly to g_Osum (this kernel initializes it) ----
    {
        int qa_ = qc * 160 + wid * 16 + lr;
        float* da = &g_Osum[((size_t)b * NTOK + pbase + qa_) * 128 + h * HD];
        float* db = &g_Osum[((size_t)b * NTOK + pbase + qa_ + 8) * 128 + h * HD];
        *(float2*)&da[2 * lc]     = make_float2(oc0[0] * inv0, oc0[1] * inv0);
        *(float2*)&da[2 * lc + 8] = make_float2(oc1[0] * inv0, oc1[1] * inv0);
        *(float2*)&db[2 * lc]     = make_float2(oc0[2] * inv1, oc0[3] * inv1);
        *(float2*)&db[2 * lc + 8] = make_float2(oc1[2] * inv1, oc1[3] * inv1);
    }

    // ---- phase switch: main-loop smem dead; load epilogue tables ----
    __syncthreads();
    for (int e = tid; e < 79 * 16; e += 320) { s.epi.rw[e] = relw[e]; s.epi.rh[e] = relh[e]; }
    for (int e = tid; e < 640; e += 320) {
        ((float*)s.epi.Vc)[e] = g_Vc40[bh * 640 + e];
        ((float*)s.epi.Vr)[e] = g_Vr40[bh * 640 + e];
    }
    __syncthreads();

    // fp32 rel-pos epilogue: 2 threads per query; RMW adds to the softmax part
    const int qloc = tid >> 1, half = tid & 1;
    const int qi = qc * 160 + qloc;
    const int r = qi / 40, c = qi - r * 40;
    float q[16];
    load16(&g_Q[(base + (bi * 40 + r) * WW + bj * 40 + c) * HD], q);
    float o[8] = {0.f, 0.f, 0.f, 0.f, 0.f, 0.f, 0.f, 0.f};
    const int off = half ? (39 - r) : (39 - c);
    const float* tbl = half ? s.epi.rh : s.epi.rw;
#pragma unroll 2
    for (int kc = 0; kc < 40; kc++) {
        const float* tp = &tbl[(kc + off) * 16];
        float mine = 0.f;
#pragma unroll
        for (int d = 0; d < 16; d++) mine = fmaf(q[d], tp[d], mine);
        float other = __shfl_xor_sync(0xffffffffu, mine, 1);
        float w  = half ? other : mine;
        float wh = half ? mine  : other;
#pragma unroll
        for (int j = 0; j < 8; j++)
            o[j] = fmaf(w, s.epi.Vc[kc][half * 8 + j], fmaf(wh, s.epi.Vr[kc][half * 8 + j], o[j]));
    }
    float* dst = &g_Osum[((size_t)b * NTOK + pbase + qi) * 128 + h * HD + half * 8];
#pragma unroll
    for (int j4b = 0; j4b < 2; j4b++) {
        float4 cur = *(float4*)&dst[4 * j4b];
        float4 val = make_float4(o[4 * j4b + 0] + cur.x, o[4 * j4b + 1] + cur.y,
                                 o[4 * j4b + 2] + cur.z, o[4 * j4b + 3] + cur.w);
        *(float4*)&dst[4 * j4b] = val;
    }
}

// ---------------- final via bf16x3 mma: out = Osum @ Wc + bc ----------------
__global__ __launch_bounds__(256) void final_mma_kernel(float* __restrict__ out) {
    __shared__ uint32_t AsH[128][9], AsL[128][9];
    __shared__ uint32_t BsH[64][9], BsL[64][9];
    const int m0 = blockIdx.x * 128;
    const int n0 = blockIdx.y * 64;
    const int tid = threadIdx.x;
    const int wid = tid >> 5, lane = tid & 31;
    const int lr = lane >> 2, lc = lane & 3;
    float c[8][4];
#pragma unroll
    for (int j = 0; j < 8; j++)
#pragma unroll
        for (int i = 0; i < 4; i++) c[j][i] = 0.f;

    for (int kc = 0; kc < 8; kc++) {
        __syncthreads();
        {
            int row = tid >> 1, hf = tid & 1;
            const float* src = &g_Osum[(size_t)(m0 + row) * 128 + kc * 16 + hf * 8];
            float4 f0 = *(const float4*)src;
            float4 f1 = *(const float4*)(src + 4);
            uint32_t h, l;
            split_pair(f0.x, f0.y, h, l); AsH[row][hf * 4 + 0] = h; AsL[row][hf * 4 + 0] = l;
            split_pair(f0.z, f0.w, h, l); AsH[row][hf * 4 + 1] = h; AsL[row][hf * 4 + 1] = l;
            split_pair(f1.x, f1.y, h, l); AsH[row][hf * 4 + 2] = h; AsL[row][hf * 4 + 2] = l;
            split_pair(f1.z, f1.w, h, l); AsH[row][hf * 4 + 3] = h; AsL[row][hf * 4 + 3] = l;
        }
#pragma unroll
        for (int ee = 0; ee < 2; ee++) {
            int e = tid + ee * 256;
            int n = e & 63, kp = e >> 6;
            float b0 = g_Wc[(size_t)(kc * 16 + 2 * kp) * 128 + n0 + n];
            float b1 = g_Wc[(size_t)(kc * 16 + 2 * kp + 1) * 128 + n0 + n];
            uint32_t h, l; split_pair(b0, b1, h, l);
            BsH[n][kp] = h; BsL[n][kp] = l;
        }
        __syncthreads();
        const int rbase = wid * 16;
        uint32_t aH0 = AsH[rbase + lr][lc],     aH1 = AsH[rbase + lr + 8][lc];
        uint32_t aH2 = AsH[rbase + lr][lc + 4], aH3 = AsH[rbase + lr + 8][lc + 4];
        uint32_t aL0 = AsL[rbase + lr][lc],     aL1 = AsL[rbase + lr + 8][lc];
        uint32_t aL2 = AsL[rbase + lr][lc + 4], aL3 = AsL[rbase + lr + 8][lc + 4];
#pragma unroll
        for (int j = 0; j < 8; j++) {
            uint32_t bH0 = BsH[8 * j + lr][lc], bH1 = BsH[8 * j + lr][lc + 4];
            uint32_t bL0 = BsL[8 * j + lr][lc], bL1 = BsL[8 * j + lr][lc + 4];
            mma_bf16(c[j][0], c[j][1], c[j][2], c[j][3], aH0, aH1, aH2, aH3, bH0, bH1);
            mma_bf16(c[j][0], c[j][1], c[j][2], c[j][3], aL0, aL1, aL2, aL3, bH0, bH1);
            mma_bf16(c[j][0], c[j][1], c[j][2], c[j][3], aH0, aH1, aH2, aH3, bL0, bL1);
        }
    }
#pragma unroll
    for (int j = 0; j < 8; j++) {
        int ncol = n0 + 8 * j + 2 * lc;
        float b0v = g_bc[ncol], b1v = g_bc[ncol + 1];
        int t0 = m0 + wid * 16 + lr;
        *(float2*)&out[(size_t)t0 * 128 + ncol] = make_float2(c[j][0] + b0v, c[j][1] + b1v);
        *(float2*)&out[(size_t)(t0 + 8) * 128 + ncol] = make_float2(c[j][2] + b0v, c[j][3] + b1v);
    }
}

// ---------------- launcher (attn40 at launch index 3 -> gets profiled) ----------------
extern "C" void kernel_launch(void* const* d_in, const int* in_sizes, int n_in,
                              void* d_out, int out_size) {
    (void)in_sizes; (void)n_in; (void)out_size;
    const float* x      = (const float*)d_in[0];
    const float* wq     = (const float*)d_in[1];
    const float* wkv    = (const float*)d_in[2];
    const float* wproj  = (const float*)d_in[3];
    const float* bproj  = (const float*)d_in[4];
    const float* wfinal = (const float*)d_in[5];
    const float* bfinal = (const float*)d_in[6];
    const float* rw0 = (const float*)d_in[7];
    const float* rh0 = (const float*)d_in[8];
    const float* rw1 = (const float*)d_in[9];
    const float* rh1 = (const float*)d_in[10];
    const float* rw2 = (const float*)d_in[11];
    const float* rh2 = (const float*)d_in[12];
    float* out = (float*)d_out;

    qkv_mma_kernel<<<dim3(100, 6), 256>>>(x, wq, wkv);            // 0
    pack40_kernel<<<1600, 256>>>();                                // 1
    vsum40_kernel<<<64, 640>>>();                                  // 2
    attn40_kernel<<<640, 320>>>(rw2, rh2);                         // 3  (STORES g_Osum)
    attn_small_kernel<4, 8, true><<<800, 128>>>(rw0, rh0);         // 4  (accumulate)
    attn_small_kernel<8, 2, true><<<800, 128>>>(rw1, rh1);         // 5  (accumulate)
    wc_kernel<<<128, 128>>>(wproj, wfinal, bproj, bfinal);         // 6
    final_mma_kernel<<<dim3(100, 2), 256>>>(out);                  // 7
}